// round 17
// baseline (speedup 1.0000x reference)
#include <cuda_runtime.h>
#include <cuda_fp16.h>

// ---------------------------------------------------------------------------
// Problem constants (IN = OUT = 4096, batch M = 512)
// ---------------------------------------------------------------------------
#define NP 4096
#define KTOP 3687.0f
#define INV_LR 100.0f
#define NUM_ITER 50

#define NSLAB 128                            // 4096 / 32 j-columns per slab

__device__ float  g_mask[NP];
__device__ __half g_Wh[(size_t)4096 * 4096];     // fp16 W (32 MB)
__device__ __half g_xh[(size_t)512 * 4096];      // fp16 x (4 MB)
__device__ int    g_slab[NSLAB];                 // per-slab tile counters (reset each call)

// ---------------------------------------------------------------------------
// Helpers
// ---------------------------------------------------------------------------
__device__ __forceinline__ void cp_async16(unsigned dst, const void* src) {
    asm volatile("cp.async.cg.shared.global [%0], [%1], 16;" :: "r"(dst), "l"(src));
}
__device__ __forceinline__ unsigned smem_u32(const void* p) {
    unsigned a;
    asm("{ .reg .u64 t; cvta.to.shared.u64 t, %1; cvt.u32.u64 %0, t; }" : "=r"(a) : "l"(p));
    return a;
}
__device__ __forceinline__ int redux_add(int v) {
    int r;
    asm volatile("redux.sync.add.s32 %0, %1, 0xffffffff;" : "=r"(r) : "r"(v));
    return r;
}
__device__ __forceinline__ void mma_f16(float* d, const unsigned* a, const unsigned* b) {
    asm volatile("mma.sync.aligned.m16n8k16.row.col.f32.f16.f16.f32 "
                 "{%0,%1,%2,%3}, {%4,%5,%6,%7}, {%8,%9}, {%0,%1,%2,%3};"
                 : "+f"(d[0]), "+f"(d[1]), "+f"(d[2]), "+f"(d[3])
                 : "r"(a[0]), "r"(a[1]), "r"(a[2]), "r"(a[3]), "r"(b[0]), "r"(b[1]));
}
__device__ __forceinline__ void ldsm4(unsigned* d, unsigned addr) {
    asm volatile("ldmatrix.sync.aligned.m8n8.x4.shared.b16 {%0,%1,%2,%3}, [%4];"
                 : "=r"(d[0]), "=r"(d[1]), "=r"(d[2]), "=r"(d[3]) : "r"(addr));
}
__device__ __forceinline__ int ld_acquire(const int* p) {
    int v;
    asm volatile("ld.acquire.gpu.global.s32 %0, [%1];" : "=r"(v) : "l"(p) : "memory");
    return v;
}
__device__ __forceinline__ void red_release_add1(int* p) {
    asm volatile("red.release.gpu.global.add.s32 [%0], 1;" :: "l"(p) : "memory");
}

// ---------------------------------------------------------------------------
// Kernel A: block 0 = counter reset + collapsed Dykstra (early exit);
//           blocks 1..2048 = rx (g_xh = fp16(x)).
// ---------------------------------------------------------------------------
__global__ __launch_bounds__(256) void prep_kernel(const float* __restrict__ alpha,
                                                   const float* __restrict__ x) {
    const int tid = threadIdx.x;
    if (blockIdx.x != 0) {
        int i = (blockIdx.x - 1) * 256 + tid;
        float4 v = ((const float4*)x)[i];
        __half2 h0 = __floats2half2_rn(v.x, v.y);
        __half2 h1 = __floats2half2_rn(v.z, v.w);
        uint2 o;
        o.x = *reinterpret_cast<unsigned*>(&h0);
        o.y = *reinterpret_cast<unsigned*>(&h1);
        ((uint2*)g_xh)[i] = o;
        return;
    }
    // reset slab counters (visible to kernel B via kernel-boundary ordering)
    if (tid < NSLAB) g_slab[tid] = 0;

    __shared__ int ctr[NUM_ITER];
    const int lane = tid & 31;
    if (tid < NUM_ITER) ctr[tid] = 0;

    float s[16];
#pragma unroll
    for (int e = 0; e < 16; e++) s[e] = alpha[e * 256 + tid] * INV_LR;
    __syncthreads();

    float D = 0.f;
    for (int it = 0; it < NUM_ITER; it++) {
        float part = 0.f;
#pragma unroll
        for (int e = 0; e < 16; e++) part += fminf(fmaxf(s[e] + D, 0.f), 1.f);
        int p = redux_add(__float2int_rn(part * 65536.0f));
        if (lane == 0) atomicAdd(&ctr[it], p);
        __syncthreads();
        float total = (float)ctr[it] * (1.0f / 65536.0f);
        float delta = (KTOP - total) * (1.0f / (float)NP);
        if (delta == 0.0f) break;        // uniform across block (ctr is shared)
        D += delta;
    }
#pragma unroll
    for (int e = 0; e < 16; e++)
        g_mask[e * 256 + tid] = fminf(fmaxf(s[e] + D, 0.f), 1.f);
}

// ---------------------------------------------------------------------------
// Kernel B (fused): blocks 0..127 = GEMM CTAs; blocks 128..639 = W builders.
//   Builder block p (=bid-128), pass q in [0,8): tile t = q*512 + p.
//     tile: j0 = (t>>5)*32 (slab t>>5), r0 = (t&31)*128.
//     After the tile's fp16 W stores: threadfence, syncthreads, red.release
//     on g_slab[t>>5]. Slab ready when counter == 32.
//   GEMM CTA: identical to the proven R16 fp16 pipeline, but each
//     LOAD_CHUNK(k) is preceded by an acquire-spin until slabs 2k, 2k+1
//     are complete. Deadlock-free: a GEMM CTA (96KB, 128thr) leaves room
//     for a builder block (96KB, 128thr) on the same SM.
// ---------------------------------------------------------------------------
#define WB_ROWS 128
#define WB_COLS 32
#define BAND_ROWS 160
#define BSTRIDE 36
#define NBUILD 512                           // builder blocks (x8 tiles = 4096)

#define BM 128
#define BN 128
#define BK 64
#define STAGES 3
#define NCHUNK 64                            // 4096 / 64
#define A_BYTES (BM * BK * 2)                // 16384
#define STAGE_BYTES (2 * A_BYTES)            // 32768 (A + B)
#define SMEM_TOTAL (STAGES * STAGE_BYTES)    // 98304

__global__ void __launch_bounds__(128, 1) fused_kernel(float* __restrict__ C,
                                                       const float* __restrict__ V) {
    extern __shared__ char smem[];
    const int tid = threadIdx.x;

    // ======================= builder path =======================
    if (blockIdx.x >= 128) {
        const int p = blockIdx.x - 128;
        float* sV = (float*)smem;            // 160*36*4 = 23040 B of the 96KB

        for (int q = 0; q < 8; q++) {
            const int t = q * NBUILD + p;
            const int j0 = (t >> 5) * WB_COLS;
            const int r0 = (t & 31) * WB_ROWS;
            const int i_min = (r0 - j0 - (WB_COLS - 1) + 2 * NP) & (NP - 1);

            for (int idx = tid; idx < BAND_ROWS * 8; idx += 128) {
                int tt = idx >> 3, u = idx & 7;
                int gi = (i_min + tt) & (NP - 1);
                float m = g_mask[gi];
                float4 v = *(const float4*)(V + (size_t)gi * 4096 + j0 + u * 4);
                float* d = &sV[tt * BSTRIDE + u * 4];
                d[0] = m * v.x; d[1] = m * v.y; d[2] = m * v.z; d[3] = m * v.w;
            }
            __syncthreads();

            const int jj4 = (tid & 7) * 4;
            const int rb = tid >> 3;         // 0..15
#pragma unroll
            for (int i = 0; i < 8; i++) {
                int rr = rb + i * 16;
                float f0 = sV[(rr - (jj4 + 0) + 31) * BSTRIDE + jj4 + 0];
                float f1 = sV[(rr - (jj4 + 1) + 31) * BSTRIDE + jj4 + 1];
                float f2 = sV[(rr - (jj4 + 2) + 31) * BSTRIDE + jj4 + 2];
                float f3 = sV[(rr - (jj4 + 3) + 31) * BSTRIDE + jj4 + 3];
                __half2 h0 = __floats2half2_rn(f0, f1);
                __half2 h1 = __floats2half2_rn(f2, f3);
                uint2 o;
                o.x = *reinterpret_cast<unsigned*>(&h0);
                o.y = *reinterpret_cast<unsigned*>(&h1);
                *(uint2*)(g_Wh + (size_t)(r0 + rr) * 4096 + j0 + jj4) = o;
            }
            __threadfence();                 // each thread fences its W stores
            __syncthreads();                 // also protects sV reuse next pass
            if (tid == 0) red_release_add1(&g_slab[t >> 5]);
        }
        return;
    }

    // ======================= GEMM path (R16-proven) =======================
    const unsigned sbase = smem_u32(smem);
    const int lane = tid & 31;
    const int warp = tid >> 5;
    const int m0 = blockIdx.y * BM;          // grid.y = 4
    const int n0 = (blockIdx.x & 31) * BN;   // 32 n-tiles in blocks 0..127? no:
    // NOTE: grid is 1-D (640). Decompose: gemm id g in [0,128): n-tile = g & 31, m-tile = g >> 5.
    const int g = blockIdx.x;
    const int mm0 = (g >> 5) * BM;
    const int nn0 = (g & 31) * BN;

    const unsigned lane7 = lane & 7;
    const unsigned hA = lane >> 4;
    const unsigned hB = (lane >> 3) & 1;
    const int wm = (warp & 1) * 64;
    const int wn = (warp >> 1) * 64;
    const int r = lane >> 2;
    const int c = lane & 3;

    const __half* __restrict__ Ag = g_xh + (size_t)mm0 * 4096;
    const __half* __restrict__ Bg = g_Wh + (size_t)nn0 * 4096;

    unsigned aoff[4], boff[4];
#pragma unroll
    for (int mt = 0; mt < 4; mt++)
        aoff[mt] = (unsigned)((wm + mt * 16 + (lane & 15)) << 7);
#pragma unroll
    for (int np = 0; np < 4; np++)
        boff[np] = (unsigned)((wn + (2 * np + (lane >> 4)) * 8 + (lane & 7)) << 7) + A_BYTES;

    float acc[4][8][4];
#pragma unroll
    for (int mt = 0; mt < 4; mt++)
#pragma unroll
        for (int nt = 0; nt < 8; nt++)
#pragma unroll
            for (int e = 0; e < 4; e++) acc[mt][nt][e] = 0.f;

    unsigned a_f[2][4][4], b_f[2][4][4];

#define WAIT_SLABS(k)                                                             \
    do {                                                                          \
        if (tid == 0) {                                                           \
            const int s0 = 2 * (k);                                               \
            while (ld_acquire(&g_slab[s0]) < 32) __nanosleep(64);                 \
            while (ld_acquire(&g_slab[s0 + 1]) < 32) __nanosleep(64);             \
        }                                                                         \
        __syncthreads();                                                          \
    } while (0)

#define LOAD_CHUNK(cc, stoff)                                                     \
    do {                                                                          \
        const unsigned aB = sbase + (stoff);                                      \
        const unsigned bB = aB + A_BYTES;                                         \
        const int kb = (cc) * BK;                                                 \
        _Pragma("unroll")                                                         \
        for (int i = 0; i < 8; i++) {                                             \
            int idx = tid + i * 128;                                              \
            int row = idx >> 3, u = idx & 7;                                      \
            unsigned sw = (unsigned)((row << 7) + ((u ^ (row & 7)) << 4));        \
            cp_async16(aB + sw, Ag + (size_t)row * 4096 + kb + u * 8);            \
        }                                                                         \
        _Pragma("unroll")                                                         \
        for (int i = 0; i < 8; i++) {                                             \
            int idx = tid + i * 128;                                              \
            int row = idx >> 3, u = idx & 7;                                      \
            unsigned sw = (unsigned)((row << 7) + ((u ^ (row & 7)) << 4));        \
            cp_async16(bB + sw, Bg + (size_t)row * 4096 + kb + u * 8);            \
        }                                                                         \
    } while (0)

#define LD_FRAG(buf, stoff, ks)                                                   \
    do {                                                                          \
        unsigned swA = ((2u * (ks) + hA) ^ lane7) << 4;                           \
        unsigned swB = ((2u * (ks) + hB) ^ lane7) << 4;                           \
        _Pragma("unroll")                                                         \
        for (int mt = 0; mt < 4; mt++)                                            \
            ldsm4(a_f[buf][mt], sbase + (stoff) + aoff[mt] + swA);                \
        _Pragma("unroll")                                                         \
        for (int np = 0; np < 4; np++)                                            \
            ldsm4(b_f[buf][np], sbase + (stoff) + boff[np] + swB);                \
    } while (0)

    WAIT_SLABS(0);
    LOAD_CHUNK(0, 0);
    asm volatile("cp.async.commit_group;" ::: "memory");
    WAIT_SLABS(1);
    LOAD_CHUNK(1, STAGE_BYTES);
    asm volatile("cp.async.commit_group;" ::: "memory");

    int st = 0;
    int lst = 2;
    for (int cc = 0; cc < NCHUNK; cc++) {
        asm volatile("cp.async.wait_group 1;" ::: "memory");   // chunk cc resident
        __syncthreads();

        if (cc + 2 < NCHUNK) {
            WAIT_SLABS(cc + 2);
            LOAD_CHUNK(cc + 2, lst * STAGE_BYTES);
        }
        asm volatile("cp.async.commit_group;" ::: "memory");

        const unsigned stoff = (unsigned)(st * STAGE_BYTES);
        LD_FRAG(0, stoff, 0);

#pragma unroll
        for (int ks = 0; ks < 4; ks++) {
            const int cur = ks & 1;
            if (ks < 3) LD_FRAG(cur ^ 1, stoff, ks + 1);
#pragma unroll
            for (int mt = 0; mt < 4; mt++)
#pragma unroll
                for (int nt = 0; nt < 8; nt++)
                    mma_f16(acc[mt][nt], a_f[cur][mt], &b_f[cur][nt >> 1][(nt & 1) * 2]);
        }

        st = (st + 1 == STAGES) ? 0 : st + 1;
        lst = (lst + 1 == STAGES) ? 0 : lst + 1;
    }

    // epilogue (fp32 C)
#pragma unroll
    for (int mt = 0; mt < 4; mt++) {
        int row = mm0 + wm + mt * 16 + r;
#pragma unroll
        for (int nt = 0; nt < 8; nt++) {
            int col = nn0 + wn + nt * 8 + 2 * c;
            *(float2*)(C + (size_t)row * 4096 + col) = make_float2(acc[mt][nt][0], acc[mt][nt][1]);
            *(float2*)(C + (size_t)(row + 8) * 4096 + col) = make_float2(acc[mt][nt][2], acc[mt][nt][3]);
        }
    }
#undef WAIT_SLABS
#undef LOAD_CHUNK
#undef LD_FRAG
}

// ---------------------------------------------------------------------------
extern "C" void kernel_launch(void* const* d_in, const int* in_sizes, int n_in,
                              void* d_out, int out_size) {
    const float* x = nullptr;
    const float* V = nullptr;
    const float* alpha = nullptr;
    for (int i = 0; i < n_in; i++) {
        if (in_sizes[i] == 512 * 4096)       x     = (const float*)d_in[i];
        else if (in_sizes[i] == 4096 * 4096) V     = (const float*)d_in[i];
        else if (in_sizes[i] == 4096)        alpha = (const float*)d_in[i];
    }

    cudaFuncSetAttribute(fused_kernel, cudaFuncAttributeMaxDynamicSharedMemorySize, SMEM_TOTAL);

    prep_kernel<<<1 + 512 * 4096 / 4 / 256, 256>>>(alpha, x);
    fused_kernel<<<128 + NBUILD, 128, SMEM_TOTAL>>>((float*)d_out, V);
}